// round 1
// baseline (speedup 1.0000x reference)
#include <cuda_runtime.h>
#include <cuda_bf16.h>
#include <cstdint>

// Problem constants
#define Bq   4
#define Nq   2048
#define FIN  128
#define Hq   4
#define Dq   64
#define HD   256          // H*D
#define ALPHA 0.2f

// Scratch (allocation-free rule: __device__ globals)
__device__ float g_h[Bq * Hq * Nq * Dq];    // h laid out [b][head][n][d]  (8 MB)
__device__ float g_o[Bq * Hq * Nq * Dq];    // per-head outputs (8 MB)
__device__ float g_ei[Bq * Hq * Nq];
__device__ float g_ej[Bq * Hq * Nq];

// ---------------------------------------------------------------------------
// Kernel 1: h = x @ W, scattered to [b][head][n][d]
// Block: 256 threads, 32 rows x 256 cols, K chunked by 32.
// ---------------------------------------------------------------------------
__global__ __launch_bounds__(256) void k_gemm(const float* __restrict__ x,
                                              const float* __restrict__ W) {
    __shared__ float Ws[32 * 256];
    __shared__ float xs[32 * 33];

    const int tid  = threadIdx.x;
    const int row0 = blockIdx.x * 32;           // global row in [0, B*N)
    const int ty   = tid >> 4;                  // 0..15 -> 2 rows each
    const int tx   = tid & 15;                  // col group: o = tx + c*16

    float acc[2][16];
#pragma unroll
    for (int r = 0; r < 2; r++)
#pragma unroll
        for (int c = 0; c < 16; c++) acc[r][c] = 0.f;

    for (int kc = 0; kc < FIN; kc += 32) {
        __syncthreads();
        // W chunk: rows kc..kc+31, 256 cols = 8192 floats = 2048 float4
        const float4* W4 = (const float4*)(W + kc * 256);
#pragma unroll
        for (int t = 0; t < 8; t++) {
            int idx = tid + 256 * t;
            ((float4*)Ws)[idx] = W4[idx];
        }
        // x chunk: 32 rows x 32 k = 256 float4, one per thread
        {
            int r  = tid >> 3;
            int kq = tid & 7;
            float4 v = *(const float4*)(x + (size_t)(row0 + r) * FIN + kc + kq * 4);
            float* dst = &xs[r * 33 + kq * 4];
            dst[0] = v.x; dst[1] = v.y; dst[2] = v.z; dst[3] = v.w;
        }
        __syncthreads();
#pragma unroll
        for (int k = 0; k < 32; k++) {
            float x0 = xs[(ty * 2 + 0) * 33 + k];
            float x1 = xs[(ty * 2 + 1) * 33 + k];
#pragma unroll
            for (int c = 0; c < 16; c++) {
                float wv = Ws[k * 256 + tx + c * 16];
                acc[0][c] = fmaf(x0, wv, acc[0][c]);
                acc[1][c] = fmaf(x1, wv, acc[1][c]);
            }
        }
    }

    // scatter to g_h[b][head][n][d]
#pragma unroll
    for (int r = 0; r < 2; r++) {
        int g = row0 + ty * 2 + r;
        int b = g / Nq;
        int n = g % Nq;
#pragma unroll
        for (int c = 0; c < 16; c++) {
            int o    = tx + c * 16;
            int head = o >> 6;
            int d    = o & 63;
            g_h[(((size_t)b * Hq + head) * Nq + n) * Dq + d] = acc[r][c];
        }
    }
}

// ---------------------------------------------------------------------------
// Kernel 2: ei/ej = h . a1 / h . a2 per (b,head,n). One warp per row.
// ---------------------------------------------------------------------------
__global__ __launch_bounds__(256) void k_ev(const float* __restrict__ a) {
    int task = blockIdx.x * 8 + (threadIdx.x >> 5);   // (b*H+head)*N + n
    int lane = threadIdx.x & 31;
    const float* hr = g_h + (size_t)task * Dq;
    float v0 = hr[lane], v1 = hr[lane + 32];
    float e1 = v0 * a[lane]      + v1 * a[lane + 32];
    float e2 = v0 * a[64 + lane] + v1 * a[96 + lane];
#pragma unroll
    for (int off = 16; off > 0; off >>= 1) {
        e1 += __shfl_down_sync(0xffffffffu, e1, off);
        e2 += __shfl_down_sync(0xffffffffu, e2, off);
    }
    if (lane == 0) {
        g_ei[task] = e1;
        g_ej[task] = e2;
    }
}

// ---------------------------------------------------------------------------
// Kernel 3: fused masked-softmax attention, one (b, head, 128-row tile) per block.
// Single pass over j (no max subtraction needed: |e| is small by construction),
// accumulating numerator O and denominator Sum(p). TJ = 32.
// Thread (ty=tid/8, tx=tid&7) owns rows i = ty*4+r and cols d = tx*8+c.
// ---------------------------------------------------------------------------
__global__ __launch_bounds__(256) void k_attn(const int* __restrict__ adj) {
    __shared__ float ei_s[128];
    __shared__ float ej_s[32];
    __shared__ float V_s[32 * 64];
    __shared__ float p_s[128 * 33];    // padded stride 33: conflict-free loads
    __shared__ float dn_s[128];

    const int tid  = threadIdx.x;
    const int bt   = blockIdx.x;
    const int it   = bt & 15;
    const int head = (bt >> 4) & 3;
    const int b    = bt >> 6;
    const int i0   = it * 128;
    const int bh   = b * Hq + head;

    const float* Vg      = g_h + (size_t)bh * Nq * Dq;
    const int*   adj_row = adj + ((size_t)b * Nq + i0) * Nq;

    if (tid < 128) ei_s[tid] = g_ei[bh * Nq + i0 + tid];

    const int ty = tid >> 3;
    const int tx = tid & 7;

    float acc[4][8];
#pragma unroll
    for (int r = 0; r < 4; r++)
#pragma unroll
        for (int c = 0; c < 8; c++) acc[r][c] = 0.f;
    float den[4] = {0.f, 0.f, 0.f, 0.f};

    for (int j0 = 0; j0 < Nq; j0 += 32) {
        __syncthreads();
        // V tile: 32 x 64 floats = 512 float4
        {
            const float4* Vt = (const float4*)(Vg + (size_t)j0 * Dq);
            ((float4*)V_s)[tid]       = Vt[tid];
            ((float4*)V_s)[tid + 256] = Vt[tid + 256];
        }
        if (tid < 32) ej_s[tid] = g_ej[bh * Nq + j0 + tid];
        __syncthreads();

        // p tile: 128 x 32, 16 elements per thread
#pragma unroll
        for (int t = 0; t < 16; t++) {
            int idx = tid + 256 * t;
            int i   = idx >> 5;
            int j   = idx & 31;
            int av  = adj_row[(size_t)i * Nq + j0 + j];
            float e = ei_s[i] + ej_s[j];
            e = (e >= 0.f) ? e : ALPHA * e;
            float p = av ? __expf(e) : 0.f;
            p_s[i * 33 + j] = p;
        }
        __syncthreads();

        // O += p * V  (register-blocked 4x8)
#pragma unroll 8
        for (int j = 0; j < 32; j++) {
            float4 v0 = *(const float4*)&V_s[j * 64 + tx * 8];
            float4 v1 = *(const float4*)&V_s[j * 64 + tx * 8 + 4];
            float p0 = p_s[(ty * 4 + 0) * 33 + j];
            float p1 = p_s[(ty * 4 + 1) * 33 + j];
            float p2 = p_s[(ty * 4 + 2) * 33 + j];
            float p3 = p_s[(ty * 4 + 3) * 33 + j];
            if (tx == 0) { den[0] += p0; den[1] += p1; den[2] += p2; den[3] += p3; }
            acc[0][0] = fmaf(p0, v0.x, acc[0][0]); acc[0][1] = fmaf(p0, v0.y, acc[0][1]);
            acc[0][2] = fmaf(p0, v0.z, acc[0][2]); acc[0][3] = fmaf(p0, v0.w, acc[0][3]);
            acc[0][4] = fmaf(p0, v1.x, acc[0][4]); acc[0][5] = fmaf(p0, v1.y, acc[0][5]);
            acc[0][6] = fmaf(p0, v1.z, acc[0][6]); acc[0][7] = fmaf(p0, v1.w, acc[0][7]);
            acc[1][0] = fmaf(p1, v0.x, acc[1][0]); acc[1][1] = fmaf(p1, v0.y, acc[1][1]);
            acc[1][2] = fmaf(p1, v0.z, acc[1][2]); acc[1][3] = fmaf(p1, v0.w, acc[1][3]);
            acc[1][4] = fmaf(p1, v1.x, acc[1][4]); acc[1][5] = fmaf(p1, v1.y, acc[1][5]);
            acc[1][6] = fmaf(p1, v1.z, acc[1][6]); acc[1][7] = fmaf(p1, v1.w, acc[1][7]);
            acc[2][0] = fmaf(p2, v0.x, acc[2][0]); acc[2][1] = fmaf(p2, v0.y, acc[2][1]);
            acc[2][2] = fmaf(p2, v0.z, acc[2][2]); acc[2][3] = fmaf(p2, v0.w, acc[2][3]);
            acc[2][4] = fmaf(p2, v1.x, acc[2][4]); acc[2][5] = fmaf(p2, v1.y, acc[2][5]);
            acc[2][6] = fmaf(p2, v1.z, acc[2][6]); acc[2][7] = fmaf(p2, v1.w, acc[2][7]);
            acc[3][0] = fmaf(p3, v0.x, acc[3][0]); acc[3][1] = fmaf(p3, v0.y, acc[3][1]);
            acc[3][2] = fmaf(p3, v0.z, acc[3][2]); acc[3][3] = fmaf(p3, v0.w, acc[3][3]);
            acc[3][4] = fmaf(p3, v1.x, acc[3][4]); acc[3][5] = fmaf(p3, v1.y, acc[3][5]);
            acc[3][6] = fmaf(p3, v1.z, acc[3][6]); acc[3][7] = fmaf(p3, v1.w, acc[3][7]);
        }
    }

    __syncthreads();
    if (tx == 0) {
#pragma unroll
        for (int r = 0; r < 4; r++) dn_s[ty * 4 + r] = den[r];
    }
    __syncthreads();

    float* og = g_o + ((size_t)bh * Nq + i0) * Dq;
#pragma unroll
    for (int r = 0; r < 4; r++) {
        float inv = 1.f / dn_s[ty * 4 + r];
        float4 w0, w1;
        w0.x = acc[r][0] * inv; w0.y = acc[r][1] * inv;
        w0.z = acc[r][2] * inv; w0.w = acc[r][3] * inv;
        w1.x = acc[r][4] * inv; w1.y = acc[r][5] * inv;
        w1.z = acc[r][6] * inv; w1.w = acc[r][7] * inv;
        *(float4*)&og[(ty * 4 + r) * Dq + tx * 8]     = w0;
        *(float4*)&og[(ty * 4 + r) * Dq + tx * 8 + 4] = w1;
    }
}

// ---------------------------------------------------------------------------
// Kernel 4: out[b][n][d] = mean over heads of g_o
// ---------------------------------------------------------------------------
__global__ __launch_bounds__(256) void k_mean(float* __restrict__ out) {
    int idx = blockIdx.x * 256 + threadIdx.x;     // over B*N*D = 524288
    if (idx >= Bq * Nq * Dq) return;
    int d = idx & 63;
    int n = (idx >> 6) & (Nq - 1);
    int b = idx >> 17;
    float s = 0.f;
#pragma unroll
    for (int h = 0; h < Hq; h++)
        s += g_o[(((size_t)b * Hq + h) * Nq + n) * Dq + d];
    out[idx] = 0.25f * s;
}

// ---------------------------------------------------------------------------
extern "C" void kernel_launch(void* const* d_in, const int* in_sizes, int n_in,
                              void* d_out, int out_size) {
    const float* x   = (const float*)d_in[0];
    const int*   adj = (const int*)  d_in[1];
    const float* W   = (const float*)d_in[2];
    const float* a   = (const float*)d_in[3];
    float*       out = (float*)d_out;

    k_gemm<<<(Bq * Nq) / 32, 256>>>(x, W);
    k_ev  <<<(Bq * Hq * Nq) / 8, 256>>>(a);
    k_attn<<<Bq * Hq * (Nq / 128), 256>>>(adj);
    k_mean<<<(Bq * Nq * Dq + 255) / 256, 256>>>(out);
}